// round 1
// baseline (speedup 1.0000x reference)
#include <cuda_runtime.h>

#define GEPS    1e-7f
#define GACLIP  (1.0f - 1e-6f)
#define GPI     3.14159274101257324f   /* float32(np.pi) */

__device__ __forceinline__ float circle_giou_loss(
    float cx0, float cy0, float r0,
    float cx1, float cy1, float r1)
{
    float dx = cx0 - cx1;
    float dy = cy0 - cy1;
    float d2 = dx * dx + dy * dy;
    float d  = sqrtf(fmaxf(d2, GEPS));

    float rmax = fmaxf(r0, r1);
    float rmin = fminf(r0, r1);
    float rdiff = rmax - rmin;

    bool lens      = (d < r0 + r1) && (d > rdiff);
    bool contained = (d <= rdiff);

    float r0sq = r0 * r0;
    float r1sq = r1 * r1;

    float cos0 = __fdividef(d2 + r0sq - r1sq, fmaxf(2.0f * d * r0, GEPS));
    cos0 = fminf(fmaxf(cos0, -GACLIP), GACLIP);
    float cos1 = __fdividef(d2 + r1sq - r0sq, fmaxf(2.0f * d * r1, GEPS));
    cos1 = fminf(fmaxf(cos1, -GACLIP), GACLIP);

    float t = (r0 + r1 - d) * (d + r0 - r1) * (d - r0 + r1) * (d + r0 + r1);
    float t_safe = lens ? fmaxf(t, GEPS) : 1.0f;

    float lens_area = r0sq * acosf(cos0) + r1sq * acosf(cos1)
                    - 0.5f * sqrtf(t_safe);

    float inter = lens ? lens_area
                       : (contained ? GPI * rmin * rmin : 0.0f);

    float uni = GPI * (r0sq + r1sq) - inter;
    float iou = __fdividef(inter, fmaxf(uni, GEPS));

    float q = __fdividef(rdiff, d);
    q = fminf(fmaxf(q, 0.0f), GACLIP);
    float alpha = acosf(q);

    float h2 = d2 - rdiff * rdiff;
    float h2_safe = contained ? 1.0f : fmaxf(h2, GEPS);

    float hull_open = rmax * rmax * (GPI - alpha)
                    + rmin * rmin * alpha
                    + (rmax + rmin) * sqrtf(h2_safe);
    float hull = contained ? GPI * rmax * rmax : hull_open;

    float giou = iou - __fdividef(hull - uni, fmaxf(hull, GEPS));
    return 1.0f - giou;
}

__global__ void giou_zero_kernel(float* __restrict__ out)
{
    *out = 0.0f;
}

__global__ __launch_bounds__(256)
void giou_kernel(const float4* __restrict__ x4,
                 const float4* __restrict__ y4,
                 float* __restrict__ out)
{
    const unsigned tid = blockIdx.x * blockDim.x + threadIdx.x;

    // Each thread handles 4 rows (12 floats = 3 float4) from x and from y.
    const unsigned base = 3u * tid;
    float4 xa = x4[base + 0];
    float4 xb = x4[base + 1];
    float4 xc = x4[base + 2];
    float4 ya = y4[base + 0];
    float4 yb = y4[base + 1];
    float4 yc = y4[base + 2];

    float acc;
    acc  = circle_giou_loss(xa.x, xa.y, xa.z,  ya.x, ya.y, ya.z);
    acc += circle_giou_loss(xa.w, xb.x, xb.y,  ya.w, yb.x, yb.y);
    acc += circle_giou_loss(xb.z, xb.w, xc.x,  yb.z, yb.w, yc.x);
    acc += circle_giou_loss(xc.y, xc.z, xc.w,  yc.y, yc.z, yc.w);

    // Warp reduce
    #pragma unroll
    for (int off = 16; off > 0; off >>= 1)
        acc += __shfl_down_sync(0xffffffffu, acc, off);

    __shared__ float warp_sums[8];
    const int lane = threadIdx.x & 31;
    const int warp = threadIdx.x >> 5;
    if (lane == 0) warp_sums[warp] = acc;
    __syncthreads();

    if (threadIdx.x < 8) {
        float v = warp_sums[threadIdx.x];
        #pragma unroll
        for (int off = 4; off > 0; off >>= 1)
            v += __shfl_down_sync(0xffu, v, off);
        if (threadIdx.x == 0)
            atomicAdd(out, v);
    }
}

extern "C" void kernel_launch(void* const* d_in, const int* in_sizes, int n_in,
                              void* d_out, int out_size)
{
    const float4* x4 = (const float4*)d_in[0];
    const float4* y4 = (const float4*)d_in[1];
    float* out = (float*)d_out;

    // N = 4194304 rows; 4 rows/thread; 256 threads/block -> 4096 blocks exact.
    const int n_rows = in_sizes[0] / 3;          // 4194304
    const int threads = 256;
    const int rows_per_block = threads * 4;      // 1024
    const int blocks = (n_rows + rows_per_block - 1) / rows_per_block;  // 4096

    giou_zero_kernel<<<1, 1>>>(out);
    giou_kernel<<<blocks, threads>>>(x4, y4, out);
}

// round 2
// speedup vs baseline: 1.2567x; 1.2567x over previous
#include <cuda_runtime.h>

#define GEPS    1e-7f
#define GACLIP  (1.0f - 1e-6f)
#define GPI     3.14159274101257324f   /* float32(np.pi) */

// sqrt via single MUFU.RSQ: valid for x > 0 (all call sites clamp >= EPS).
__device__ __forceinline__ float fsqrt_pos(float x)
{
    return x * rsqrtf(x);
}

// Abramowitz-Stegun 4.4.45: acos(x) ~= sqrt(1-x)*(a0 + a1 x + a2 x^2 + a3 x^3)
// for x in [0,1], max abs err 6.8e-5 rad. Reflect for negative x.
__device__ __forceinline__ float acos_fast_abs(float xa)  // xa in [0, 1)
{
    float p = fmaf(-0.0187293f, xa, 0.0742610f);
    p = fmaf(p, xa, -0.2121144f);
    p = fmaf(p, xa, 1.5707288f);
    return fsqrt_pos(1.0f - xa) * p;
}

__device__ __forceinline__ float acos_fast(float x)       // x in (-1, 1)
{
    float xa = fabsf(x);
    float r = acos_fast_abs(xa);
    return (x >= 0.0f) ? r : (GPI - r);
}

__device__ __forceinline__ float circle_giou_loss(
    float cx0, float cy0, float r0,
    float cx1, float cy1, float r1)
{
    float dx = cx0 - cx1;
    float dy = cy0 - cy1;
    float d2 = fmaf(dx, dx, dy * dy);
    float d  = fsqrt_pos(fmaxf(d2, GEPS));

    float rmax = fmaxf(r0, r1);
    float rmin = fminf(r0, r1);
    float rdiff = rmax - rmin;

    bool lens      = (d < r0 + r1) && (d > rdiff);
    bool contained = (d <= rdiff);

    float r0sq = r0 * r0;
    float r1sq = r1 * r1;

    float cos0 = __fdividef(d2 + r0sq - r1sq, fmaxf(2.0f * d * r0, GEPS));
    cos0 = fminf(fmaxf(cos0, -GACLIP), GACLIP);
    float cos1 = __fdividef(d2 + r1sq - r0sq, fmaxf(2.0f * d * r1, GEPS));
    cos1 = fminf(fmaxf(cos1, -GACLIP), GACLIP);

    float t = (r0 + r1 - d) * (d + r0 - r1) * (d - r0 + r1) * (d + r0 + r1);
    float t_safe = lens ? fmaxf(t, GEPS) : 1.0f;

    float lens_area = r0sq * acos_fast(cos0) + r1sq * acos_fast(cos1)
                    - 0.5f * fsqrt_pos(t_safe);

    float inter = lens ? lens_area
                       : (contained ? GPI * rmin * rmin : 0.0f);

    float uni = GPI * (r0sq + r1sq) - inter;
    float iou = __fdividef(inter, fmaxf(uni, GEPS));

    // q in [0, ACLIP]: positive branch of acos only.
    float q = __fdividef(rdiff, d);
    q = fminf(fmaxf(q, 0.0f), GACLIP);
    float alpha = acos_fast_abs(q);

    float h2 = d2 - rdiff * rdiff;
    float h2_safe = contained ? 1.0f : fmaxf(h2, GEPS);

    float hull_open = rmax * rmax * (GPI - alpha)
                    + rmin * rmin * alpha
                    + (rmax + rmin) * fsqrt_pos(h2_safe);
    float hull = contained ? GPI * rmax * rmax : hull_open;

    float giou = iou - __fdividef(hull - uni, fmaxf(hull, GEPS));
    return 1.0f - giou;
}

__global__ void giou_zero_kernel(float* __restrict__ out)
{
    *out = 0.0f;
}

__global__ __launch_bounds__(256)
void giou_kernel(const float4* __restrict__ x4,
                 const float4* __restrict__ y4,
                 float* __restrict__ out)
{
    const unsigned tid = blockIdx.x * blockDim.x + threadIdx.x;

    // Each thread handles 4 rows (12 floats = 3 float4) from x and from y.
    const unsigned base = 3u * tid;
    float4 xa = x4[base + 0];
    float4 xb = x4[base + 1];
    float4 xc = x4[base + 2];
    float4 ya = y4[base + 0];
    float4 yb = y4[base + 1];
    float4 yc = y4[base + 2];

    float acc;
    acc  = circle_giou_loss(xa.x, xa.y, xa.z,  ya.x, ya.y, ya.z);
    acc += circle_giou_loss(xa.w, xb.x, xb.y,  ya.w, yb.x, yb.y);
    acc += circle_giou_loss(xb.z, xb.w, xc.x,  yb.z, yb.w, yc.x);
    acc += circle_giou_loss(xc.y, xc.z, xc.w,  yc.y, yc.z, yc.w);

    // Warp reduce
    #pragma unroll
    for (int off = 16; off > 0; off >>= 1)
        acc += __shfl_down_sync(0xffffffffu, acc, off);

    __shared__ float warp_sums[8];
    const int lane = threadIdx.x & 31;
    const int warp = threadIdx.x >> 5;
    if (lane == 0) warp_sums[warp] = acc;
    __syncthreads();

    if (threadIdx.x < 8) {
        float v = warp_sums[threadIdx.x];
        #pragma unroll
        for (int off = 4; off > 0; off >>= 1)
            v += __shfl_down_sync(0xffu, v, off);
        if (threadIdx.x == 0)
            atomicAdd(out, v);
    }
}

extern "C" void kernel_launch(void* const* d_in, const int* in_sizes, int n_in,
                              void* d_out, int out_size)
{
    const float4* x4 = (const float4*)d_in[0];
    const float4* y4 = (const float4*)d_in[1];
    float* out = (float*)d_out;

    const int n_rows = in_sizes[0] / 3;          // 4194304
    const int threads = 256;
    const int rows_per_block = threads * 4;      // 1024
    const int blocks = (n_rows + rows_per_block - 1) / rows_per_block;  // 4096

    giou_zero_kernel<<<1, 1>>>(out);
    giou_kernel<<<blocks, threads>>>(x4, y4, out);
}